// round 16
// baseline (speedup 1.0000x reference)
#include <cuda_runtime.h>

// CoupledClustersLossV2 — ticketed quarter-class runs, static inner body.
// embeddings: [256 cls][2 pos/neg][32 samples][2048] fp32 = 128 MB.
// ||x - a||^2 = ||x||^2 - (x·s)/16 + ||s||^2/1024,  s = sum of 32 pos rows.
//
// R15 analysis: busy SMs (2 classes = 1MB) run at 40GB/s; static partitions
// can't beat max=1MB at occ 2 (any quantum rounds up). So work is pulled
// dynamically: 296 persistent CTAs grab quarter-class runs (512 cols =
// 2 chunks of CHUNK=256) from a global ticket. Replay-safe without resets:
// each CTA exits on its FIRST invalid ticket -> grabs per replay are exactly
// NRUNS + GRID = 1320, so run = ticket % 1320 (valid < 1024). Inner 2-chunk
// body is R15's proven machinery verbatim (static stages, phase1 -> one
// BAR -> phase3 re-read, neg rows direct __ldcg, self-visible cp.async).
// tid0 grabs the next ticket during chunk0-phase1; the chunk0 barrier
// broadcasts it, so next-run prefetch issues into freed stages and the
// copy pipe never drains across runs. Combine: 4 static slots per class +
// epoch counters; all sums fixed-order -> deterministic.

#define NCLS     256
#define NS       32
#define DIM      2048
#define CHUNK    256
#define THREADS  256
#define GRID     296
#define NRUNS    1024                          // 256 classes x 4 quarters
#define TOTGRAB  (NRUNS + GRID)                // 1320 grabs per replay
#define TILE_F4  2048                          // pos tile: 32 rows x 64 f4 = 32KB
#define SMEM_BYTES (2 * TILE_F4 * 16 + 2 * 8 * 64 * 16)   // 81920
#define ROW_F4   (DIM / 4)                     // 512
#define MARGIN   0.3f

// per-(class, quarter) row partials: 0=||pos||^2 1=pos·s 2=||neg||^2 3=neg·s
__device__ float        g_scratch[NCLS][4][4][NS];
__device__ unsigned int g_ticket;              // monotone ticket (never reset)
__device__ unsigned int g_done[NCLS];          // epoch counters (never reset)
__device__ float        g_class_loss[NCLS];
__device__ unsigned int g_cls_done;            // epoch counter (never reset)

__device__ __forceinline__ float dot4(float4 a, float4 b) {
    return fmaf(a.x, b.x, fmaf(a.y, b.y, fmaf(a.z, b.z, a.w * b.w)));
}
__device__ __forceinline__ float wsum(float v) {
#pragma unroll
    for (int o = 16; o > 0; o >>= 1) v += __shfl_xor_sync(0xffffffffu, v, o);
    return v;
}
__device__ __forceinline__ void cp_async16(unsigned smem_dst, const float4* gsrc) {
    asm volatile("cp.async.cg.shared.global [%0], [%1], 16;\n"
                 :: "r"(smem_dst), "l"(gsrc));
}
__device__ __forceinline__ void f4add(float4& a, float4 b) {
    a.x += b.x; a.y += b.y; a.z += b.z; a.w += b.w;
}

__global__ __launch_bounds__(THREADS, 2)
void ccl_kernel(const float* __restrict__ emb, float* __restrict__ out)
{
    extern __shared__ float4 sh4[];                       // [2][TILE_F4] pos tiles
    float4* spart = sh4 + 2 * TILE_F4;                    // [2][8][64] f4 partials
    __shared__ unsigned s_next;

    const int tid  = threadIdx.x;
    const int warp = tid >> 5;
    const int lane = tid & 31;

    // Thread's tile slots: pos rows warp+8i (i=0..3), f4-cols lane, lane+32.
    const unsigned slot0  = (unsigned)((warp * 64 + lane) * 16);
    const unsigned smbase = (unsigned)__cvta_generic_to_shared(sh4);
    const float4*  ebase  = (const float4*)emb + (size_t)warp * ROW_F4 + lane;

    // float4 base for a run: class*2*NS*DIM/4 + quarter*512/4.
    auto run_base = [&](unsigned r) -> const float4* {
        return ebase + ((size_t)(r >> 2) << 15) + ((r & 3u) << 7);
    };
    // Issue pos chunk ci (0/1) of run r into stage ci: this thread's 8 slots.
    auto issue = [&](const float4* gq, int ci) {
        const float4*  g  = gq + (ci << 6);               // ci * CHUNK/4
        const unsigned sb = smbase + (unsigned)ci * (TILE_F4 * 16);
#pragma unroll
        for (int i = 0; i < 4; ++i) {
            cp_async16(sb + slot0 + i * 8192u,        g + (size_t)(i * 8) * ROW_F4);
            cp_async16(sb + slot0 + 512u + i * 8192u, g + (size_t)(i * 8) * ROW_F4 + 32);
        }
        asm volatile("cp.async.commit_group;\n" ::);
    };

    // ---- prologue: grab first run, prefetch both of its chunks ----
    if (tid == 0) s_next = atomicAdd(&g_ticket, 1u) % TOTGRAB;
    __syncthreads();
    unsigned run = s_next;
    const float4* gq = run_base(run);
    if (run < NRUNS) { issue(gq, 0); issue(gq, 1); }

    while (run < NRUNS) {
        float pn[4] = {0.f,0.f,0.f,0.f};
        float tp[4] = {0.f,0.f,0.f,0.f};
        float nn[4] = {0.f,0.f,0.f,0.f};
        float tn[4] = {0.f,0.f,0.f,0.f};
        unsigned nxt;
        const float4* gn = gq;   // next-run base (set after chunk0 barrier)

#pragma unroll
        for (int ci = 0; ci < 2; ++ci) {
            const float4* tile = sh4 + ci * TILE_F4;

            // Neg rows straight from GMEM, before the wait (latency hides).
            float4 n[8];
#pragma unroll
            for (int i = 0; i < 4; ++i) {
                n[2*i]   = __ldcg(gq + (ci << 6) + (size_t)(NS + i * 8) * ROW_F4);
                n[2*i+1] = __ldcg(gq + (ci << 6) + (size_t)(NS + i * 8) * ROW_F4 + 32);
            }

            if (ci == 0) {
                // Grab next ticket; chunk0's barrier broadcasts it.
                if (tid == 0) s_next = atomicAdd(&g_ticket, 1u) % TOTGRAB;
                // Pending: {c0, c1} -> wait_group 1 drains c0 (self-visible).
                asm volatile("cp.async.wait_group 1;\n" ::);
            } else {
                // Pending: {c1, next.c0?}. Tail (no next.c0): drain fully.
                if (nxt < NRUNS) asm volatile("cp.async.wait_group 1;\n" ::);
                else             asm volatile("cp.async.wait_group 0;\n" ::);
            }

            // Phase 1: stream p transiently -> pn + per-warp colsum partials.
            float4 sp0 = {0.f,0.f,0.f,0.f}, sp1 = {0.f,0.f,0.f,0.f};
#pragma unroll
            for (int i = 0; i < 4; ++i) {
                const float4 p0 = tile[(warp + i * 8) * 64 + lane];
                const float4 p1 = tile[(warp + i * 8) * 64 + lane + 32];
                pn[i] += dot4(p0, p0) + dot4(p1, p1);
                f4add(sp0, p0); f4add(sp1, p1);
                nn[i] += dot4(n[2*i], n[2*i]) + dot4(n[2*i+1], n[2*i+1]);
            }
            spart[(ci * 8 + warp) * 64 + lane]      = sp0;
            spart[(ci * 8 + warp) * 64 + lane + 32] = sp1;

            __syncthreads();   // the ONLY per-chunk barrier (also publishes s_next)

            if (ci == 0) { nxt = s_next; gn = run_base(nxt); }

            // Phase 3: gather column sums, re-read p from tile, accumulate.
            float4 sc0 = spart[(ci * 8 + 0) * 64 + lane];
            float4 sc1 = spart[(ci * 8 + 0) * 64 + lane + 32];
#pragma unroll
            for (int w = 1; w < 8; ++w) {
                f4add(sc0, spart[(ci * 8 + w) * 64 + lane]);
                f4add(sc1, spart[(ci * 8 + w) * 64 + lane + 32]);
            }
#pragma unroll
            for (int i = 0; i < 4; ++i) {
                const float4 p0 = tile[(warp + i * 8) * 64 + lane];
                const float4 p1 = tile[(warp + i * 8) * 64 + lane + 32];
                tp[i] += dot4(p0, sc0) + dot4(p1, sc1);
                tn[i] += dot4(n[2*i], sc0) + dot4(n[2*i+1], sc1);
            }

            // Refill this stage with next run's chunk ci (slots fully re-read).
            if (nxt < NRUNS) issue(gn, ci);
        }

        // ---- run flush: publish this quarter's row partials ----
        const int cls  = (int)(run >> 2);
        const int slot = (int)(run & 3u);
#pragma unroll
        for (int i = 0; i < 4; ++i) {
            const float a = wsum(pn[i]);
            const float b = wsum(tp[i]);
            const float d = wsum(nn[i]);
            const float e = wsum(tn[i]);
            if (lane == 0) {
                const int row = warp + i * 8;
                g_scratch[cls][slot][0][row] = a;
                g_scratch[cls][slot][1][row] = b;
                g_scratch[cls][slot][2][row] = d;
                g_scratch[cls][slot][3][row] = e;
            }
        }
        __syncthreads();       // all warps' STGs issued before the count

        if (warp == 0) {       // warps 1-7 roll into the next run immediately
            unsigned fin = 0;
            if (lane == 0) {
                __threadfence();                    // publish scratch
                const unsigned old = atomicAdd(&g_done[cls], 1u);
                fin = ((old & 3u) == 3u) ? 1u : 0u;
            }
            fin = __shfl_sync(0xffffffffu, fin, 0);
            if (fin) {
                // ---- per-class finisher (fixed-order sums) ----
                __threadfence();
                float fpn = 0.f, ftp = 0.f, fnn = 0.f, ftn = 0.f;
#pragma unroll
                for (int s = 0; s < 4; ++s) {
                    fpn += __ldcg(&g_scratch[cls][s][0][lane]);
                    ftp += __ldcg(&g_scratch[cls][s][1][lane]);
                    fnn += __ldcg(&g_scratch[cls][s][2][lane]);
                    ftn += __ldcg(&g_scratch[cls][s][3][lane]);
                }
                const float ssum  = wsum(ftp);              // ||s||^2
                const float anorm = ssum * (1.0f / 1024.0f);
                const float ap2   = fpn - ftp * (1.0f / 16.0f) + anorm;
                const float nd2   = fnn - ftn * (1.0f / 16.0f) + anorm;

                float mn = nd2;
#pragma unroll
                for (int o = 16; o > 0; o >>= 1)
                    mn = fminf(mn, __shfl_xor_sync(0xffffffffu, mn, o));
                const float an = sqrtf(fmaxf(mn, 0.f));

                float t = fmaxf(sqrtf(fmaxf(ap2, 0.f)) - an + MARGIN, 0.f);
                const float term = wsum(t * t);

                unsigned old2 = 0;
                if (lane == 0) {
                    g_class_loss[cls] = term;
                    __threadfence();
                    old2 = atomicAdd(&g_cls_done, 1u);
                }
                old2 = __shfl_sync(0xffffffffu, old2, 0);
                if ((old2 & (NCLS - 1u)) == (NCLS - 1u)) {
                    // ---- global finisher: fixed-order mean ----
                    __threadfence();
                    float v = 0.f;
#pragma unroll
                    for (int q = 0; q < NCLS / 32; ++q)
                        v += __ldcg(&g_class_loss[q * 32 + lane]);
                    v = wsum(v);
                    if (lane == 0) out[0] = v * (1.0f / (float)NCLS);
                }
            }
        }

        run = nxt;
        gq  = gn;
    }
}

extern "C" void kernel_launch(void* const* d_in, const int* in_sizes, int n_in,
                              void* d_out, int out_size)
{
    (void)in_sizes; (void)n_in; (void)out_size;
    const float* emb = (const float*)d_in[0];   // [16384, 2048] fp32
    // d_in[1] (target) is unused by the reference computation.
    cudaFuncSetAttribute(ccl_kernel, cudaFuncAttributeMaxDynamicSharedMemorySize,
                         SMEM_BYTES);
    ccl_kernel<<<GRID, THREADS, SMEM_BYTES>>>(emb, (float*)d_out);
}

// round 17
// speedup vs baseline: 1.1965x; 1.1965x over previous
#include <cuda_runtime.h>

// CoupledClustersLossV2 — R15 (best: 27.1us) + neg-latency hiding. HBM-bound.
// embeddings: [256 cls][2 pos/neg][32 samples][2048] fp32 = 128 MB.
// ||x - a||^2 = ||x||^2 - (x·s)/16 + ||s||^2/1024,  s = sum of 32 pos rows.
//
// R11/R14/R16 (three strikes): every dynamic/balance scheme loses more in
// pipeline continuity than the 1.18x wave imbalance costs. So: R15 structure
// verbatim, and attack per-busy-SM throughput (40 vs 54.6 GB/s) instead.
// Change 1: nn/tn (all uses of neg rows) moved to phase 3 — the 8 __ldcg
// neg loads issued at chunk top now have phase1+STS+BAR+gather (~600+ cyc)
// to land instead of ~10 instructions; register lifetime unchanged (n lived
// to phase3 for tn anyway). Change 2: prefetch.global.L2 for chunk c+2's
// neg lines (zero regs, issue-only) so the __ldcg hits L2, not DRAM.
// Proven skeleton: 256 CTAs x 256 thr (one class each), CHUNK=256, 2-stage
// self-visible cp.async pos tiles (thread copies exactly the slots it reads
// -> no tile barrier), ONE barrier per chunk (colsum exchange), phase3
// re-reads p from SMEM (no register blowup), single end-of-CTA flush,
// epoch-counter finishers (replay-safe), fixed-order sums (deterministic).

#define NCLS     256
#define NS       32
#define DIM      2048
#define CHUNK    256                          // columns per chunk
#define THREADS  256
#define NCH      8                            // DIM / CHUNK, compile-time
#define TILE_F4  2048                         // pos tile: 32 rows x 64 f4 = 32KB
#define SPART_F4 (8 * 64)                     // 8 warps x 64 f4 cols
#define SMEM_BYTES (2 * TILE_F4 * 16 + 2 * SPART_F4 * 16)   // 81920
#define ROW_F4   (DIM / 4)                    // 512
#define MARGIN   0.3f

__device__ float        g_class_loss[NCLS];
__device__ unsigned int g_cls_done;           // epoch counter (never reset)

__device__ __forceinline__ float dot4(float4 a, float4 b) {
    return fmaf(a.x, b.x, fmaf(a.y, b.y, fmaf(a.z, b.z, a.w * b.w)));
}
__device__ __forceinline__ float wsum(float v) {
#pragma unroll
    for (int o = 16; o > 0; o >>= 1) v += __shfl_xor_sync(0xffffffffu, v, o);
    return v;
}
__device__ __forceinline__ void cp_async16(unsigned smem_dst, const float4* gsrc) {
    asm volatile("cp.async.cg.shared.global [%0], [%1], 16;\n"
                 :: "r"(smem_dst), "l"(gsrc));
}
__device__ __forceinline__ void prefetch_l2(const void* p) {
    asm volatile("prefetch.global.L2 [%0];" :: "l"(p));
}
__device__ __forceinline__ void f4add(float4& a, float4 b) {
    a.x += b.x; a.y += b.y; a.z += b.z; a.w += b.w;
}

__global__ __launch_bounds__(THREADS, 2)
void ccl_kernel(const float* __restrict__ emb, float* __restrict__ out)
{
    extern __shared__ float4 sh4[];                       // [2][TILE_F4] pos tiles
    float4* spart = sh4 + 2 * TILE_F4;                    // [2][8][64] f4 partials
    __shared__ float red[4][NS];                          // flush staging

    const int cls  = blockIdx.x;
    const int tid  = threadIdx.x;
    const int warp = tid >> 5;
    const int lane = tid & 31;

    // Thread's tile slots: pos rows warp+8i (i=0..3), f4-cols lane and lane+32.
    // Tile layout: row r at r*64 f4 (1024B); row step 8 -> 8192B.
    const unsigned slot0  = (unsigned)((warp * 64 + lane) * 16);
    const unsigned smbase = (unsigned)__cvta_generic_to_shared(sh4);
    const float4*  gbase  = (const float4*)emb + ((size_t)cls << 15)   // 2*NS*DIM/4
                            + (size_t)warp * ROW_F4 + lane;

    // Issue pos chunk c into stage (c&1): this thread's own 8 slots.
    auto issue = [&](int c) {
        const float4*  g  = gbase + (c << 6);             // c * CHUNK/4
        const unsigned sb = smbase + (unsigned)(c & 1) * (TILE_F4 * 16);
#pragma unroll
        for (int i = 0; i < 4; ++i) {
            cp_async16(sb + slot0 + i * 8192u,        g + (size_t)(i * 8) * ROW_F4);
            cp_async16(sb + slot0 + 512u + i * 8192u, g + (size_t)(i * 8) * ROW_F4 + 32);
        }
        asm volatile("cp.async.commit_group;\n" ::);
    };

    issue(0); issue(1);
    // Warm L2 for chunk 0/1 neg rows (they are __ldcg'd, not cp.async'd).
#pragma unroll
    for (int i = 0; i < 4; ++i) {
        prefetch_l2(gbase + (size_t)(NS + i * 8) * ROW_F4);
        prefetch_l2(gbase + (1 << 6) + (size_t)(NS + i * 8) * ROW_F4);
    }

    float pn[4] = {0.f,0.f,0.f,0.f};
    float tp[4] = {0.f,0.f,0.f,0.f};
    float nn[4] = {0.f,0.f,0.f,0.f};
    float tn[4] = {0.f,0.f,0.f,0.f};

#pragma unroll
    for (int c = 0; c < NCH; ++c) {
        const int sb = c & 1;
        const float4* tile = sh4 + sb * TILE_F4;

        // Neg rows straight from GMEM (coalesced), issued at chunk top; first
        // USE is in phase 3, so phase1+STS+BAR+gather (~600+ cyc) hides the
        // load latency. .cg = streaming, no L1 pollution.
        float4 n[8];
#pragma unroll
        for (int i = 0; i < 4; ++i) {
            n[2*i]   = __ldcg(gbase + (c << 6) + (size_t)(NS + i * 8) * ROW_F4);
            n[2*i+1] = __ldcg(gbase + (c << 6) + (size_t)(NS + i * 8) * ROW_F4 + 32);
        }

        // Self-visibility: we read only our own cp.async copies -> no barrier.
        if (c + 1 < NCH) asm volatile("cp.async.wait_group 1;\n" ::);
        else             asm volatile("cp.async.wait_group 0;\n" ::);

        // Phase 1: stream p transiently -> pn + per-warp colsum partials.
        // (neg rows intentionally untouched here — their loads are in flight)
        float4 sp0 = {0.f,0.f,0.f,0.f}, sp1 = {0.f,0.f,0.f,0.f};
#pragma unroll
        for (int i = 0; i < 4; ++i) {
            const float4 p0 = tile[(warp + i * 8) * 64 + lane];
            const float4 p1 = tile[(warp + i * 8) * 64 + lane + 32];
            pn[i] += dot4(p0, p0) + dot4(p1, p1);
            f4add(sp0, p0); f4add(sp1, p1);
        }
        spart[(sb * 8 + warp) * 64 + lane]      = sp0;
        spart[(sb * 8 + warp) * 64 + lane + 32] = sp1;

        __syncthreads();   // the ONLY per-chunk barrier (colsum exchange)

        // Phase 3: gather full column sums, re-read p from tile, accumulate
        // all four quantities (nn/tn consume n here, ~600 cyc after issue).
        float4 sc0 = spart[(sb * 8 + 0) * 64 + lane];
        float4 sc1 = spart[(sb * 8 + 0) * 64 + lane + 32];
#pragma unroll
        for (int w = 1; w < 8; ++w) {
            f4add(sc0, spart[(sb * 8 + w) * 64 + lane]);
            f4add(sc1, spart[(sb * 8 + w) * 64 + lane + 32]);
        }
#pragma unroll
        for (int i = 0; i < 4; ++i) {
            const float4 p0 = tile[(warp + i * 8) * 64 + lane];
            const float4 p1 = tile[(warp + i * 8) * 64 + lane + 32];
            tp[i] += dot4(p0, sc0) + dot4(p1, sc1);
            nn[i] += dot4(n[2*i], n[2*i]) + dot4(n[2*i+1], n[2*i+1]);
            tn[i] += dot4(n[2*i], sc0) + dot4(n[2*i+1], sc1);
        }

        // Refill this stage (our own, now fully re-read slots) and warm L2
        // for chunk c+2's neg rows (zero registers, issue-only).
        if (c + 2 < NCH) {
            issue(c + 2);
#pragma unroll
            for (int i = 0; i < 4; ++i)
                prefetch_l2(gbase + ((c + 2) << 6) + (size_t)(NS + i * 8) * ROW_F4);
        }
        // spart[sb] rewritten at chunk c+2 phase1, i.e. after barrier c+1 -> safe.
    }

    // ---- single end-of-CTA flush: class loss computed entirely in-CTA ----
#pragma unroll
    for (int i = 0; i < 4; ++i) {
        const float a = wsum(pn[i]);
        const float b = wsum(tp[i]);
        const float d = wsum(nn[i]);
        const float e = wsum(tn[i]);
        if (lane == 0) {
            const int row = warp + i * 8;
            red[0][row] = a;
            red[1][row] = b;
            red[2][row] = d;
            red[3][row] = e;
        }
    }
    __syncthreads();

    if (warp == 0) {
        const float pnv = red[0][lane];
        const float tpv = red[1][lane];
        const float nnv = red[2][lane];
        const float tnv = red[3][lane];

        const float ssum  = wsum(tpv);                 // ||s||^2
        const float anorm = ssum * (1.0f / 1024.0f);   // ||s||^2 / 32^2
        const float ap2   = pnv - tpv * (1.0f / 16.0f) + anorm;
        const float nd2   = nnv - tnv * (1.0f / 16.0f) + anorm;

        float mn = nd2;
#pragma unroll
        for (int o = 16; o > 0; o >>= 1)
            mn = fminf(mn, __shfl_xor_sync(0xffffffffu, mn, o));
        const float an = sqrtf(fmaxf(mn, 0.f));

        float t = fmaxf(sqrtf(fmaxf(ap2, 0.f)) - an + MARGIN, 0.f);
        const float term = wsum(t * t);

        unsigned old = 0;
        if (lane == 0) {
            g_class_loss[cls] = term;
            __threadfence();
            old = atomicAdd(&g_cls_done, 1u);
        }
        old = __shfl_sync(0xffffffffu, old, 0);
        if ((old & (NCLS - 1u)) == (NCLS - 1u)) {
            // ---- global finisher: fixed-order mean over 256 class losses ----
            __threadfence();
            float v = 0.f;
#pragma unroll
            for (int q = 0; q < NCLS / 32; ++q)
                v += __ldcg(&g_class_loss[q * 32 + lane]);
            v = wsum(v);
            if (lane == 0) out[0] = v * (1.0f / (float)NCLS);
        }
    }
}

extern "C" void kernel_launch(void* const* d_in, const int* in_sizes, int n_in,
                              void* d_out, int out_size)
{
    (void)in_sizes; (void)n_in; (void)out_size;
    const float* emb = (const float*)d_in[0];   // [16384, 2048] fp32
    // d_in[1] (target) is unused by the reference computation.
    cudaFuncSetAttribute(ccl_kernel, cudaFuncAttributeMaxDynamicSharedMemorySize,
                         SMEM_BYTES);
    ccl_kernel<<<NCLS, THREADS, SMEM_BYTES>>>(emb, (float*)d_out);
}